// round 15
// baseline (speedup 1.0000x reference)
#include <cuda_runtime.h>
#include <math.h>
#include <cstdint>

// Problem constants
#define BATCH 2
#define SEQL 2048
#define NTOK (BATCH * SEQL)          // 4096
#define DMODEL 512
#define ED 1024
#define DSTATE 16
#define DCONV 4
#define DTRANK 32
#define NLAYERS 2

// Scratch buffers (no cudaMalloc allowed)
__device__ float g_xz[NTOK * 2 * ED];
__device__ float g_xic[NTOK * ED];
__device__ float g_dbc[NTOK * 64];
__device__ float g_dbcp[8 * NTOK * 64];   // split-K partials for x_proj
__device__ float g_delta[NTOK * ED];
__device__ float g_y[NTOK * ED];

__device__ __forceinline__ float softplus_f(float v) {
    return (v > 20.f) ? v : log1pf(__expf(v));
}
__device__ __forceinline__ float silu_f(float v) {
    return __fdividef(v, 1.f + __expf(-v));
}

// ---------------------------------------------------------------------------
// Packed fp32 helpers (Blackwell f32x2)
// ---------------------------------------------------------------------------
typedef unsigned long long u64t;

__device__ __forceinline__ u64t dup2f(float v) {
    u64t r; unsigned u = __float_as_uint(v);
    asm("mov.b64 %0, {%1, %1};" : "=l"(r) : "r"(u));
    return r;
}
__device__ __forceinline__ void ffma2(u64t& c, u64t a, u64t b) {
    asm("fma.rn.f32x2 %0, %1, %2, %0;" : "+l"(c) : "l"(a), "l"(b));
}
__device__ __forceinline__ float2 unpack2(u64t p) {
    unsigned lo, hi;
    asm("mov.b64 {%0, %1}, %2;" : "=r"(lo), "=r"(hi) : "l"(p));
    return make_float2(__uint_as_float(lo), __uint_as_float(hi));
}

// Smem sizing shared between host and kernel (dynamic smem)
#define GEMM_STA 132
#define GEMM_STB(TN) ((TN) + 4)
#define GEMM_SA_BYTES(BKv) (2 * (BKv) * GEMM_STA * 4)
#define GEMM_SB_BYTES(TN, BKv) (2 * (BKv) * GEMM_STB(TN) * 4)
#define GEMM_SMEM(TN, BKv) \
    (GEMM_SA_BYTES(BKv) + GEMM_SB_BYTES(TN, BKv) + 512)

// ---------------------------------------------------------------------------
// fp32 FFMA2 GEMM:  C[M,N] (=, +=) A[M,K] @ W[N,K]^T
// BM=128, BN=TILE_N (128/64), BK template (16/32), 256 threads, double-
// buffered k-major smem, two __syncthreads per k-tile (BK=32 halves barrier
// count vs BK=16). B-fragment columns split into 4-wide groups 32 apart
// (TC=8): conflict-free LDS.128. Inner loop identical to R12.
// Options: +bias, +softplus, NORMW, ROWSCALE, SPLITK, SILUZ (silu on n0>=ED).
// ---------------------------------------------------------------------------
template <int TILE_N, int BK, bool BIAS, bool ACCUM, bool SOFTPLUS, bool NORMW,
          bool ROWSCALE, int SPLITK = 1, bool SILUZ = false>
__global__ __launch_bounds__(256) void fgemm(
    const float* __restrict__ A, int lda,
    const float* __restrict__ W, int ldw,
    const float* __restrict__ bias,
    const float* __restrict__ nw,
    float* __restrict__ C, int ldc, int K)
{
    constexpr int STA = GEMM_STA, STB = GEMM_STB(TILE_N);
    constexpr int NBCH = TILE_N / 64;        // B row-chunks per thread
    constexpr int NKCH = BK / 16;            // k-chunks per tile (1 or 2)
    constexpr int TC = TILE_N / 16;          // thread cols: 8 or 4
    constexpr int NQ = TC / 4;               // 4-wide col groups

    extern __shared__ char dynsmem[];
    float* sA   = (float*)dynsmem;                                 // [2][BK*STA]
    float* sB   = (float*)(dynsmem + GEMM_SA_BYTES(BK));           // [2][BK*STB]
    float* rbuf = (float*)(dynsmem + GEMM_SA_BYTES(BK) + GEMM_SB_BYTES(TILE_N, BK));

    const int tid = threadIdx.x;
    const int wid = tid >> 5, lane = tid & 31;
    const int ly = lane >> 3, lx = lane & 7;
    const int wy = wid >> 1, wx = wid & 1;
    const int rb = wy * 32 + ly * 8;
    const int cbase = wx * (TILE_N / 2) + lx * 4;
    const int m0 = blockIdx.y * 128;
    const int n0 = blockIdx.x * TILE_N;

    if (SPLITK > 1) {
        const int ks = blockIdx.z * (K / SPLITK);
        A += ks; W += ks;
        C += (size_t)blockIdx.z * gridDim.y * 128 * ldc;
        K = K / SPLITK;
    }

    const int arow = tid >> 2, aq = tid & 3;

    u64t cpk[4][TC] = {};
    float sq0 = 0.f, sq1 = 0.f;
    const int KT = K / BK;

    float4 va0[NKCH], va1[NKCH], vb0[NKCH], vb1[NKCH], vnw[NKCH];
    #pragma unroll
    for (int c = 0; c < NKCH; c++) {
        const int kk = c * 16 + aq * 4;
        va0[c] = *(const float4*)&A[(size_t)(m0 + arow) * lda + kk];
        va1[c] = *(const float4*)&A[(size_t)(m0 + arow + 64) * lda + kk];
        vb0[c] = *(const float4*)&W[(size_t)(n0 + arow) * ldw + kk];
        if (NBCH == 2)
            vb1[c] = *(const float4*)&W[(size_t)(n0 + arow + 64) * ldw + kk];
        if (NORMW) vnw[c] = *(const float4*)&nw[kk];
    }

    for (int kt = 0; kt < KT; kt++) {
        const int buf = kt & 1;
        #pragma unroll
        for (int c = 0; c < NKCH; c++) {
            {
                float* d0 = &sA[buf * BK * STA + (c * 16 + aq * 4) * STA + arow];
                d0[0] = va0[c].x; d0[STA] = va0[c].y;
                d0[2 * STA] = va0[c].z; d0[3 * STA] = va0[c].w;
                float* d1 = d0 + 64;
                d1[0] = va1[c].x; d1[STA] = va1[c].y;
                d1[2 * STA] = va1[c].z; d1[3 * STA] = va1[c].w;
            }
            if (ROWSCALE) {
                sq0 = fmaf(va0[c].x, va0[c].x, fmaf(va0[c].y, va0[c].y,
                      fmaf(va0[c].z, va0[c].z, fmaf(va0[c].w, va0[c].w, sq0))));
                sq1 = fmaf(va1[c].x, va1[c].x, fmaf(va1[c].y, va1[c].y,
                      fmaf(va1[c].z, va1[c].z, fmaf(va1[c].w, va1[c].w, sq1))));
            }
            {
                float4 b0 = vb0[c], b1 = vb1[c];
                if (NORMW) {
                    b0.x *= vnw[c].x; b0.y *= vnw[c].y;
                    b0.z *= vnw[c].z; b0.w *= vnw[c].w;
                    if (NBCH == 2) {
                        b1.x *= vnw[c].x; b1.y *= vnw[c].y;
                        b1.z *= vnw[c].z; b1.w *= vnw[c].w;
                    }
                }
                float* d0 = &sB[buf * BK * STB + (c * 16 + aq * 4) * STB + arow];
                d0[0] = b0.x; d0[STB] = b0.y; d0[2 * STB] = b0.z; d0[3 * STB] = b0.w;
                if (NBCH == 2) {
                    float* d1 = d0 + 64;
                    d1[0] = b1.x; d1[STB] = b1.y; d1[2 * STB] = b1.z; d1[3 * STB] = b1.w;
                }
            }
        }
        __syncthreads();

        if (kt + 1 < KT) {
            #pragma unroll
            for (int c = 0; c < NKCH; c++) {
                const int k0 = (kt + 1) * BK + c * 16 + aq * 4;
                va0[c] = *(const float4*)&A[(size_t)(m0 + arow) * lda + k0];
                va1[c] = *(const float4*)&A[(size_t)(m0 + arow + 64) * lda + k0];
                vb0[c] = *(const float4*)&W[(size_t)(n0 + arow) * ldw + k0];
                if (NBCH == 2)
                    vb1[c] = *(const float4*)&W[(size_t)(n0 + arow + 64) * ldw + k0];
                if (NORMW) vnw[c] = *(const float4*)&nw[k0];
            }
        }

        const float* bufA = &sA[buf * BK * STA];
        const float* bufB = &sB[buf * BK * STB];
        #pragma unroll
        for (int k = 0; k < BK; k++) {
            const ulonglong2 a0 = *(const ulonglong2*)&bufA[k * STA + rb];
            const ulonglong2 a1 = *(const ulonglong2*)&bufA[k * STA + rb + 4];
            const u64t ap[4] = {a0.x, a0.y, a1.x, a1.y};
            float4 b0 = *(const float4*)&bufB[k * STB + cbase];
            float4 b1;
            if (NQ == 2) b1 = *(const float4*)&bufB[k * STB + cbase + 32];
            u64t bd[TC];
            bd[0] = dup2f(b0.x); bd[1] = dup2f(b0.y);
            bd[2] = dup2f(b0.z); bd[3] = dup2f(b0.w);
            if (NQ == 2) {
                bd[4] = dup2f(b1.x); bd[5] = dup2f(b1.y);
                bd[6] = dup2f(b1.z); bd[7] = dup2f(b1.w);
            }
            #pragma unroll
            for (int ih = 0; ih < 4; ih++)
                #pragma unroll
                for (int j = 0; j < TC; j++)
                    ffma2(cpk[ih][j], ap[ih], bd[j]);
        }
        __syncthreads();
    }

    if (ROWSCALE) {
        float s0 = sq0 + __shfl_xor_sync(0xffffffffu, sq0, 1);
        s0 += __shfl_xor_sync(0xffffffffu, s0, 2);
        float s1 = sq1 + __shfl_xor_sync(0xffffffffu, sq1, 1);
        s1 += __shfl_xor_sync(0xffffffffu, s1, 2);
        if ((lane & 3) == 0) {
            rbuf[arow]      = rsqrtf(s0 / (float)K + 1e-5f);
            rbuf[arow + 64] = rsqrtf(s1 / (float)K + 1e-5f);
        }
        __syncthreads();
    }

    const bool do_silu = SILUZ && (n0 >= ED);

    float bias_r[TC];
    if (BIAS) {
        #pragma unroll
        for (int q = 0; q < NQ; q++) {
            float4 bb = *(const float4*)&bias[n0 + cbase + q * 32];
            bias_r[q * 4 + 0] = bb.x; bias_r[q * 4 + 1] = bb.y;
            bias_r[q * 4 + 2] = bb.z; bias_r[q * 4 + 3] = bb.w;
        }
    }
    #pragma unroll
    for (int ih = 0; ih < 4; ih++) {
        float lo[TC], hi[TC];
        #pragma unroll
        for (int j = 0; j < TC; j++) {
            float2 f = unpack2(cpk[ih][j]);
            lo[j] = f.x; hi[j] = f.y;
        }
        #pragma unroll
        for (int half = 0; half < 2; half++) {
            const float* src = half ? hi : lo;
            const int rt = rb + 2 * ih + half;
            const int row = m0 + rt;
            const float scale = ROWSCALE ? rbuf[rt] : 1.f;
            #pragma unroll
            for (int q = 0; q < NQ; q++) {
                float* cp = &C[(size_t)row * ldc + n0 + cbase + q * 32];
                float4 v = make_float4(src[q * 4 + 0], src[q * 4 + 1],
                                       src[q * 4 + 2], src[q * 4 + 3]);
                if (ROWSCALE) { v.x *= scale; v.y *= scale; v.z *= scale; v.w *= scale; }
                if (BIAS) {
                    v.x += bias_r[q * 4 + 0]; v.y += bias_r[q * 4 + 1];
                    v.z += bias_r[q * 4 + 2]; v.w += bias_r[q * 4 + 3];
                }
                if (SOFTPLUS) {
                    v.x = softplus_f(v.x); v.y = softplus_f(v.y);
                    v.z = softplus_f(v.z); v.w = softplus_f(v.w);
                }
                if (SILUZ) {
                    if (do_silu) {
                        v.x = silu_f(v.x); v.y = silu_f(v.y);
                        v.z = silu_f(v.z); v.w = silu_f(v.w);
                    }
                }
                if (ACCUM) {
                    float4 o = *(const float4*)cp;
                    v.x += o.x; v.y += o.y; v.z += o.z; v.w += o.w;
                }
                *(float4*)cp = v;
            }
        }
    }
}

// ---------------------------------------------------------------------------
// Reduce 8 split-K partials: out[i] = sum_s part[s][i]  (float4-wide)
// ---------------------------------------------------------------------------
__global__ void reduce8_kernel(const float* __restrict__ part,
                               float* __restrict__ out)
{
    const int i = (blockIdx.x * 256 + threadIdx.x) * 4;
    const int n = NTOK * 64;
    float4 s = *(const float4*)&part[i];
    #pragma unroll
    for (int k = 1; k < 8; k++) {
        float4 v = *(const float4*)&part[i + k * n];
        s.x += v.x; s.y += v.y; s.z += v.z; s.w += v.w;
    }
    *(float4*)&out[i] = s;
}

// ---------------------------------------------------------------------------
// Depthwise causal conv (k=4) + bias + silu (fast-div).
// Each thread: 4 consecutive tokens x 4 channels (7 float4 loads, 16 outputs).
// ---------------------------------------------------------------------------
__device__ __forceinline__ float getc(float4 v, int k) {
    return k == 0 ? v.x : k == 1 ? v.y : k == 2 ? v.z : v.w;
}
__device__ __forceinline__ float4 silu4(float4 a) {
    a.x = silu_f(a.x); a.y = silu_f(a.y);
    a.z = silu_f(a.z); a.w = silu_f(a.w);
    return a;
}

__global__ void conv_kernel(const float* __restrict__ xz,
                            const float* __restrict__ cw,
                            const float* __restrict__ cb,
                            float* __restrict__ out)
{
    const int idx = blockIdx.x * blockDim.x + threadIdx.x;   // NTOK/4 * ED/4
    const int e4 = (idx & 255) << 2;
    const int tq = idx >> 8;                 // token quad
    const int tloc = (tq * 4) & (SEQL - 1);  // local pos of first token

    const float4 bias = *(const float4*)&cb[e4];
    const float4 w0 = *(const float4*)&cw[(e4 + 0) * DCONV];
    const float4 w1 = *(const float4*)&cw[(e4 + 1) * DCONV];
    const float4 w2 = *(const float4*)&cw[(e4 + 2) * DCONV];
    const float4 w3 = *(const float4*)&cw[(e4 + 3) * DCONV];

    float4 xv[7];
    #pragma unroll
    for (int s = 0; s < 7; s++) {
        const int tl = tloc - 3 + s;
        xv[s] = (tl >= 0)
            ? *(const float4*)&xz[((size_t)tq * 4 + (s - 3)) * (2 * ED) + e4]
            : make_float4(0.f, 0.f, 0.f, 0.f);
    }

    #pragma unroll
    for (int o = 0; o < 4; o++) {
        float4 acc = bias;
        #pragma unroll
        for (int k = 0; k < DCONV; k++) {
            const float4 v = xv[o + k];
            acc.x = fmaf(getc(w0, k), v.x, acc.x);
            acc.y = fmaf(getc(w1, k), v.y, acc.y);
            acc.z = fmaf(getc(w2, k), v.z, acc.z);
            acc.w = fmaf(getc(w3, k), v.w, acc.w);
        }
        *(float4*)&out[((size_t)tq * 4 + o) * ED + e4] = silu4(acc);
    }
}

// ---------------------------------------------------------------------------
// Selective scan + gating (R10 layout). One warp = 4 channels; 8 lanes per
// channel, each lane owns an adjacent state pair (LDG.64 B/C). 8-token
// software pipeline. z half of xz already silu'd (SILUZ epilogue).
// ---------------------------------------------------------------------------
__global__ __launch_bounds__(128) void scan_kernel(
    const float* __restrict__ delta,
    const float* __restrict__ xi,
    const float* __restrict__ dbc,
    const float* __restrict__ xz,
    const float* __restrict__ A_log,
    const float* __restrict__ Dp,
    float* __restrict__ y)
{
    const int lane = threadIdx.x & 31;
    const int warp = threadIdx.x >> 5;
    const int ch = lane >> 3;                 // channel within warp
    const int j  = lane & 7;                  // state pair (2j, 2j+1)
    const int c = blockIdx.x * 16 + warp * 4 + ch;
    const int b = c >> 10;
    const int e = c & (ED - 1);

    const float a0 = -__expf(A_log[e * DSTATE + 2 * j]);
    const float a1 = -__expf(A_log[e * DSTATE + 2 * j + 1]);
    const float Dv = Dp[e];

    const float* dptr = delta + (size_t)b * SEQL * ED + e;
    const float* xptr = xi    + (size_t)b * SEQL * ED + e;
    const float* bcp  = dbc   + (size_t)b * SEQL * 64 + DTRANK + 2 * j;
    const float* zptr = xz    + (size_t)b * SEQL * (2 * ED) + ED + e;
    float*       yptr = y     + (size_t)b * SEQL * ED + e;

    constexpr int PF = 8;
    float cdv[PF], cxv[PF], czv[PF];
    float2 cB[PF], cC[PF];
    #pragma unroll
    for (int i = 0; i < PF; i++) {
        cdv[i] = __ldg(&dptr[(size_t)i * ED]);
        cxv[i] = __ldg(&xptr[(size_t)i * ED]);
        czv[i] = __ldg(&zptr[(size_t)i * (2 * ED)]);
        cB[i] = __ldg((const float2*)&bcp[i * 64]);
        cC[i] = __ldg((const float2*)&bcp[i * 64 + DSTATE]);
    }

    float h0 = 0.f, h1 = 0.f;
    for (int t0 = 0; t0 < SEQL; t0 += PF) {
        float ndv[PF], nxv[PF], nzv[PF];
        float2 nB[PF], nC[PF];
        if (t0 + PF < SEQL) {
            #pragma unroll
            for (int i = 0; i < PF; i++) {
                const int t = t0 + PF + i;
                ndv[i] = __ldg(&dptr[(size_t)t * ED]);
                nxv[i] = __ldg(&xptr[(size_t)t * ED]);
                nzv[i] = __ldg(&zptr[(size_t)t * (2 * ED)]);
                nB[i] = __ldg((const float2*)&bcp[t * 64]);
                nC[i] = __ldg((const float2*)&bcp[t * 64 + DSTATE]);
            }
        }
        #pragma unroll
        for (int i = 0; i < PF; i++) {
            const float dA0 = __expf(cdv[i] * a0);
            const float dA1 = __expf(cdv[i] * a1);
            const float u = cdv[i] * cxv[i];
            h0 = fmaf(dA0, h0, u * cB[i].x);
            h1 = fmaf(dA1, h1, u * cB[i].y);
            float p = fmaf(h1, cC[i].y, h0 * cC[i].x);
            p += __shfl_xor_sync(0xffffffffu, p, 4);
            p += __shfl_xor_sync(0xffffffffu, p, 2);
            p += __shfl_xor_sync(0xffffffffu, p, 1);
            if (j == 0) {
                // czv already = silu(z) (applied in in_proj epilogue)
                yptr[(size_t)(t0 + i) * ED] = (p + Dv * cxv[i]) * czv[i];
            }
        }
        #pragma unroll
        for (int i = 0; i < PF; i++) {
            cdv[i] = ndv[i]; cxv[i] = nxv[i]; czv[i] = nzv[i];
            cB[i] = nB[i]; cC[i] = nC[i];
        }
    }
}

// ---------------------------------------------------------------------------
// Host launch
// ---------------------------------------------------------------------------
extern "C" void kernel_launch(void* const* d_in, const int* in_sizes, int n_in,
                              void* d_out, int out_size)
{
    const float* x        = (const float*)d_in[0];
    const float* emb_w    = (const float*)d_in[1];
    const float* emb_b    = (const float*)d_in[2];
    const float* in_w     = (const float*)d_in[3];
    const float* conv_w   = (const float*)d_in[4];
    const float* conv_b   = (const float*)d_in[5];
    const float* xp_w     = (const float*)d_in[6];
    const float* dt_w     = (const float*)d_in[7];
    const float* dt_b     = (const float*)d_in[8];
    const float* A_log    = (const float*)d_in[9];
    const float* Dparam   = (const float*)d_in[10];
    const float* out_w    = (const float*)d_in[11];
    const float* norm_w   = (const float*)d_in[12];
    float* h = (float*)d_out;

    float *xz, *xic, *dbc, *dbcp, *delta, *yb;
    cudaGetSymbolAddress((void**)&xz,    g_xz);
    cudaGetSymbolAddress((void**)&xic,   g_xic);
    cudaGetSymbolAddress((void**)&dbc,   g_dbc);
    cudaGetSymbolAddress((void**)&dbcp,  g_dbcp);
    cudaGetSymbolAddress((void**)&delta, g_delta);
    cudaGetSymbolAddress((void**)&yb,    g_y);

    constexpr int SM128 = GEMM_SMEM(128, 32);   // 68608 B (opt-in)
    constexpr int SM64  = GEMM_SMEM(64, 16);    // 26112 B

    // Idempotent opt-in for >48KB dynamic smem on the BK=32 instantiations
    cudaFuncSetAttribute(fgemm<128, 32, true, false, false, false, false>,
        cudaFuncAttributeMaxDynamicSharedMemorySize, SM128);
    cudaFuncSetAttribute(fgemm<128, 32, false, false, false, true, true, 1, true>,
        cudaFuncAttributeMaxDynamicSharedMemorySize, SM128);
    cudaFuncSetAttribute(fgemm<128, 32, true, false, true, false, false>,
        cudaFuncAttributeMaxDynamicSharedMemorySize, SM128);
    cudaFuncSetAttribute(fgemm<128, 32, false, true, false, false, false>,
        cudaFuncAttributeMaxDynamicSharedMemorySize, SM128);

    // Embedding: h = x @ emb_w^T + emb_b  (M=4096, N=512, K=64)
    fgemm<128, 32, true, false, false, false, false>
        <<<dim3(DMODEL / 128, NTOK / 128), 256, SM128>>>(
        x, 64, emb_w, 64, emb_b, nullptr, h, DMODEL, 64);

    for (int layer = 0; layer < NLAYERS; layer++) {
        const float* l_in_w   = in_w   + (size_t)layer * 2 * ED * DMODEL;
        const float* l_conv_w = conv_w + (size_t)layer * ED * DCONV;
        const float* l_conv_b = conv_b + (size_t)layer * ED;
        const float* l_xp_w   = xp_w   + (size_t)layer * 64 * ED;
        const float* l_dt_w   = dt_w   + (size_t)layer * ED * DTRANK;
        const float* l_dt_b   = dt_b   + (size_t)layer * ED;
        const float* l_A_log  = A_log  + (size_t)layer * ED * DSTATE;
        const float* l_D      = Dparam + (size_t)layer * ED;
        const float* l_out_w  = out_w  + (size_t)layer * DMODEL * ED;
        const float* l_norm_w = norm_w + (size_t)layer * DMODEL;

        // 1+2. xz = rmsnorm(h) @ in_proj^T, norm fused; z half gets silu
        //      in the epilogue (M=4096, N=2048, K=512)
        fgemm<128, 32, false, false, false, true, true, 1, true>
            <<<dim3(2 * ED / 128, NTOK / 128), 256, SM128>>>(
            h, DMODEL, l_in_w, DMODEL, nullptr, l_norm_w, xz, 2 * ED, DMODEL);

        // 3. xi = silu(conv(xz[:, :ED]) + cb)
        conv_kernel<<<(NTOK / 4) * (ED / 4) / 256, 256>>>(
            xz, l_conv_w, l_conv_b, xic);

        // 4. dbc = xi @ x_proj^T  (M=4096, N=64, K=1024) — split-K=8
        fgemm<64, 16, false, false, false, false, false, 8>
            <<<dim3(1, NTOK / 128, 8), 256, SM64>>>(
            xic, ED, l_xp_w, ED, nullptr, nullptr, dbcp, 64, ED);
        reduce8_kernel<<<(NTOK * 64 / 4) / 256, 256>>>(dbcp, dbc);

        // 5. delta = softplus(dbc[:, :32] @ dt_proj^T + dt_b)  (M=4096, N=1024, K=32)
        fgemm<128, 32, true, false, true, false, false>
            <<<dim3(ED / 128, NTOK / 128), 256, SM128>>>(
            dbc, 64, l_dt_w, DTRANK, l_dt_b, nullptr, delta, ED, DTRANK);

        // 6. scan + gating -> y  (z pre-silu'd)
        scan_kernel<<<(BATCH * ED) / 16, 128>>>(delta, xic, dbc, xz,
                                                l_A_log, l_D, yb);

        // 7. h += y @ out_proj^T  (M=4096, N=512, K=1024)
        fgemm<128, 32, false, true, false, false, false>
            <<<dim3(DMODEL / 128, NTOK / 128), 256, SM128>>>(
            yb, ED, l_out_w, ED, nullptr, nullptr, h, DMODEL, ED);
    }
}

// round 16
// speedup vs baseline: 1.0123x; 1.0123x over previous
#include <cuda_runtime.h>
#include <math.h>
#include <cstdint>

// Problem constants
#define BATCH 2
#define SEQL 2048
#define NTOK (BATCH * SEQL)          // 4096
#define DMODEL 512
#define ED 1024
#define DSTATE 16
#define DCONV 4
#define DTRANK 32
#define NLAYERS 2

// Scratch buffers (no cudaMalloc allowed)
__device__ float g_xz[NTOK * 2 * ED];
__device__ float g_xic[NTOK * ED];
__device__ float g_dbc[NTOK * 64];
__device__ float g_dbcp[8 * NTOK * 64];   // split-K partials for x_proj
__device__ float g_delta[NTOK * ED];
__device__ float g_y[NTOK * ED];

__device__ __forceinline__ float softplus_f(float v) {
    return (v > 20.f) ? v : log1pf(__expf(v));
}
__device__ __forceinline__ float silu_f(float v) {
    return __fdividef(v, 1.f + __expf(-v));
}

// ---------------------------------------------------------------------------
// Packed fp32 helpers (Blackwell f32x2)
// ---------------------------------------------------------------------------
typedef unsigned long long u64t;

__device__ __forceinline__ u64t dup2f(float v) {
    u64t r; unsigned u = __float_as_uint(v);
    asm("mov.b64 %0, {%1, %1};" : "=l"(r) : "r"(u));
    return r;
}
__device__ __forceinline__ void ffma2(u64t& c, u64t a, u64t b) {
    asm("fma.rn.f32x2 %0, %1, %2, %0;" : "+l"(c) : "l"(a), "l"(b));
}
__device__ __forceinline__ float2 unpack2(u64t p) {
    unsigned lo, hi;
    asm("mov.b64 {%0, %1}, %2;" : "=r"(lo), "=r"(hi) : "l"(p));
    return make_float2(__uint_as_float(lo), __uint_as_float(hi));
}

// ---------------------------------------------------------------------------
// fp32 FFMA2 GEMM:  C[M,N] (=, +=) A[M,K] @ W[N,K]^T   (R12 configuration)
// BM=128, BN=TILE_N (128/64), BK=16, 256 threads, smem k-major double buffer,
// two __syncthreads per k-tile. B-fragment columns split into 4-wide groups
// 32 apart (TC=8): conflict-free LDS.128.
// Options: +bias, +softplus, NORMW, ROWSCALE, SPLITK, SILUZ (silu on n0>=ED).
// ---------------------------------------------------------------------------
template <int TILE_N, bool BIAS, bool ACCUM, bool SOFTPLUS, bool NORMW,
          bool ROWSCALE, int SPLITK = 1, bool SILUZ = false>
__global__ __launch_bounds__(256) void fgemm(
    const float* __restrict__ A, int lda,
    const float* __restrict__ W, int ldw,
    const float* __restrict__ bias,
    const float* __restrict__ nw,
    float* __restrict__ C, int ldc, int K)
{
    constexpr int BK = 16, STA = 132, STB = TILE_N + 4;
    constexpr int NBCH = TILE_N / 64;
    constexpr int TC = TILE_N / 16;
    constexpr int NQ = TC / 4;

    __shared__ float sA[2][BK * STA];
    __shared__ float sB[2][BK * STB];
    __shared__ float rbuf[128];

    const int tid = threadIdx.x;
    const int wid = tid >> 5, lane = tid & 31;
    const int ly = lane >> 3, lx = lane & 7;
    const int wy = wid >> 1, wx = wid & 1;
    const int rb = wy * 32 + ly * 8;
    const int cbase = wx * (TILE_N / 2) + lx * 4;
    const int m0 = blockIdx.y * 128;
    const int n0 = blockIdx.x * TILE_N;

    if (SPLITK > 1) {
        const int ks = blockIdx.z * (K / SPLITK);
        A += ks; W += ks;
        C += (size_t)blockIdx.z * gridDim.y * 128 * ldc;
        K = K / SPLITK;
    }

    const int arow = tid >> 2, aq = tid & 3;

    u64t cpk[4][TC] = {};
    float sq0 = 0.f, sq1 = 0.f;
    const int KT = K / BK;

    float4 va0, va1, vb0, vnw;
    float4 vb1 = make_float4(0.f, 0.f, 0.f, 0.f);
    va0 = *(const float4*)&A[(size_t)(m0 + arow) * lda + aq * 4];
    va1 = *(const float4*)&A[(size_t)(m0 + arow + 64) * lda + aq * 4];
    vb0 = *(const float4*)&W[(size_t)(n0 + arow) * ldw + aq * 4];
    if (NBCH == 2) vb1 = *(const float4*)&W[(size_t)(n0 + arow + 64) * ldw + aq * 4];
    if (NORMW) vnw = *(const float4*)&nw[aq * 4];

    for (int kt = 0; kt < KT; kt++) {
        const int buf = kt & 1;
        {
            float* d0 = &sA[buf][(aq * 4) * STA + arow];
            d0[0] = va0.x; d0[STA] = va0.y; d0[2 * STA] = va0.z; d0[3 * STA] = va0.w;
            float* d1 = d0 + 64;
            d1[0] = va1.x; d1[STA] = va1.y; d1[2 * STA] = va1.z; d1[3 * STA] = va1.w;
        }
        if (ROWSCALE) {
            sq0 = fmaf(va0.x, va0.x, fmaf(va0.y, va0.y,
                  fmaf(va0.z, va0.z, fmaf(va0.w, va0.w, sq0))));
            sq1 = fmaf(va1.x, va1.x, fmaf(va1.y, va1.y,
                  fmaf(va1.z, va1.z, fmaf(va1.w, va1.w, sq1))));
        }
        {
            float4 b0 = vb0, b1 = vb1;
            if (NORMW) {
                b0.x *= vnw.x; b0.y *= vnw.y; b0.z *= vnw.z; b0.w *= vnw.w;
                if (NBCH == 2) {
                    b1.x *= vnw.x; b1.y *= vnw.y; b1.z *= vnw.z; b1.w *= vnw.w;
                }
            }
            float* d0 = &sB[buf][(aq * 4) * STB + arow];
            d0[0] = b0.x; d0[STB] = b0.y; d0[2 * STB] = b0.z; d0[3 * STB] = b0.w;
            if (NBCH == 2) {
                float* d1 = d0 + 64;
                d1[0] = b1.x; d1[STB] = b1.y; d1[2 * STB] = b1.z; d1[3 * STB] = b1.w;
            }
        }
        __syncthreads();

        if (kt + 1 < KT) {
            const int k0 = (kt + 1) * BK;
            va0 = *(const float4*)&A[(size_t)(m0 + arow) * lda + k0 + aq * 4];
            va1 = *(const float4*)&A[(size_t)(m0 + arow + 64) * lda + k0 + aq * 4];
            vb0 = *(const float4*)&W[(size_t)(n0 + arow) * ldw + k0 + aq * 4];
            if (NBCH == 2)
                vb1 = *(const float4*)&W[(size_t)(n0 + arow + 64) * ldw + k0 + aq * 4];
            if (NORMW) vnw = *(const float4*)&nw[k0 + aq * 4];
        }

        const float* bufA = sA[buf];
        const float* bufB = sB[buf];
        #pragma unroll
        for (int k = 0; k < BK; k++) {
            const ulonglong2 a0 = *(const ulonglong2*)&bufA[k * STA + rb];
            const ulonglong2 a1 = *(const ulonglong2*)&bufA[k * STA + rb + 4];
            const u64t ap[4] = {a0.x, a0.y, a1.x, a1.y};
            float4 b0 = *(const float4*)&bufB[k * STB + cbase];
            float4 b1;
            if (NQ == 2) b1 = *(const float4*)&bufB[k * STB + cbase + 32];
            u64t bd[TC];
            bd[0] = dup2f(b0.x); bd[1] = dup2f(b0.y);
            bd[2] = dup2f(b0.z); bd[3] = dup2f(b0.w);
            if (NQ == 2) {
                bd[4] = dup2f(b1.x); bd[5] = dup2f(b1.y);
                bd[6] = dup2f(b1.z); bd[7] = dup2f(b1.w);
            }
            #pragma unroll
            for (int ih = 0; ih < 4; ih++)
                #pragma unroll
                for (int j = 0; j < TC; j++)
                    ffma2(cpk[ih][j], ap[ih], bd[j]);
        }
        __syncthreads();
    }

    if (ROWSCALE) {
        float s0 = sq0 + __shfl_xor_sync(0xffffffffu, sq0, 1);
        s0 += __shfl_xor_sync(0xffffffffu, s0, 2);
        float s1 = sq1 + __shfl_xor_sync(0xffffffffu, sq1, 1);
        s1 += __shfl_xor_sync(0xffffffffu, s1, 2);
        if ((lane & 3) == 0) {
            rbuf[arow]      = rsqrtf(s0 / (float)K + 1e-5f);
            rbuf[arow + 64] = rsqrtf(s1 / (float)K + 1e-5f);
        }
        __syncthreads();
    }

    const bool do_silu = SILUZ && (n0 >= ED);

    float bias_r[TC];
    if (BIAS) {
        #pragma unroll
        for (int q = 0; q < NQ; q++) {
            float4 bb = *(const float4*)&bias[n0 + cbase + q * 32];
            bias_r[q * 4 + 0] = bb.x; bias_r[q * 4 + 1] = bb.y;
            bias_r[q * 4 + 2] = bb.z; bias_r[q * 4 + 3] = bb.w;
        }
    }
    #pragma unroll
    for (int ih = 0; ih < 4; ih++) {
        float lo[TC], hi[TC];
        #pragma unroll
        for (int j = 0; j < TC; j++) {
            float2 f = unpack2(cpk[ih][j]);
            lo[j] = f.x; hi[j] = f.y;
        }
        #pragma unroll
        for (int half = 0; half < 2; half++) {
            const float* src = half ? hi : lo;
            const int rt = rb + 2 * ih + half;
            const int row = m0 + rt;
            const float scale = ROWSCALE ? rbuf[rt] : 1.f;
            #pragma unroll
            for (int q = 0; q < NQ; q++) {
                float* cp = &C[(size_t)row * ldc + n0 + cbase + q * 32];
                float4 v = make_float4(src[q * 4 + 0], src[q * 4 + 1],
                                       src[q * 4 + 2], src[q * 4 + 3]);
                if (ROWSCALE) { v.x *= scale; v.y *= scale; v.z *= scale; v.w *= scale; }
                if (BIAS) {
                    v.x += bias_r[q * 4 + 0]; v.y += bias_r[q * 4 + 1];
                    v.z += bias_r[q * 4 + 2]; v.w += bias_r[q * 4 + 3];
                }
                if (SOFTPLUS) {
                    v.x = softplus_f(v.x); v.y = softplus_f(v.y);
                    v.z = softplus_f(v.z); v.w = softplus_f(v.w);
                }
                if (SILUZ) {
                    if (do_silu) {
                        v.x = silu_f(v.x); v.y = silu_f(v.y);
                        v.z = silu_f(v.z); v.w = silu_f(v.w);
                    }
                }
                if (ACCUM) {
                    float4 o = *(const float4*)cp;
                    v.x += o.x; v.y += o.y; v.z += o.z; v.w += o.w;
                }
                *(float4*)cp = v;
            }
        }
    }
}

// ---------------------------------------------------------------------------
// Reduce 8 split-K partials: out[i] = sum_s part[s][i]  (float4-wide)
// ---------------------------------------------------------------------------
__global__ void reduce8_kernel(const float* __restrict__ part,
                               float* __restrict__ out)
{
    const int i = (blockIdx.x * 256 + threadIdx.x) * 4;
    const int n = NTOK * 64;
    float4 s = *(const float4*)&part[i];
    #pragma unroll
    for (int k = 1; k < 8; k++) {
        float4 v = *(const float4*)&part[i + k * n];
        s.x += v.x; s.y += v.y; s.z += v.z; s.w += v.w;
    }
    *(float4*)&out[i] = s;
}

// ---------------------------------------------------------------------------
// Depthwise causal conv (k=4) + bias + silu (fast-div).
// Each thread: 4 consecutive tokens x 4 channels (7 float4 loads, 16 outputs).
// ---------------------------------------------------------------------------
__device__ __forceinline__ float getc(float4 v, int k) {
    return k == 0 ? v.x : k == 1 ? v.y : k == 2 ? v.z : v.w;
}
__device__ __forceinline__ float4 silu4(float4 a) {
    a.x = silu_f(a.x); a.y = silu_f(a.y);
    a.z = silu_f(a.z); a.w = silu_f(a.w);
    return a;
}

__global__ void conv_kernel(const float* __restrict__ xz,
                            const float* __restrict__ cw,
                            const float* __restrict__ cb,
                            float* __restrict__ out)
{
    const int idx = blockIdx.x * blockDim.x + threadIdx.x;   // NTOK/4 * ED/4
    const int e4 = (idx & 255) << 2;
    const int tq = idx >> 8;                 // token quad
    const int tloc = (tq * 4) & (SEQL - 1);  // local pos of first token

    const float4 bias = *(const float4*)&cb[e4];
    const float4 w0 = *(const float4*)&cw[(e4 + 0) * DCONV];
    const float4 w1 = *(const float4*)&cw[(e4 + 1) * DCONV];
    const float4 w2 = *(const float4*)&cw[(e4 + 2) * DCONV];
    const float4 w3 = *(const float4*)&cw[(e4 + 3) * DCONV];

    float4 xv[7];
    #pragma unroll
    for (int s = 0; s < 7; s++) {
        const int tl = tloc - 3 + s;
        xv[s] = (tl >= 0)
            ? *(const float4*)&xz[((size_t)tq * 4 + (s - 3)) * (2 * ED) + e4]
            : make_float4(0.f, 0.f, 0.f, 0.f);
    }

    #pragma unroll
    for (int o = 0; o < 4; o++) {
        float4 acc = bias;
        #pragma unroll
        for (int k = 0; k < DCONV; k++) {
            const float4 v = xv[o + k];
            acc.x = fmaf(getc(w0, k), v.x, acc.x);
            acc.y = fmaf(getc(w1, k), v.y, acc.y);
            acc.z = fmaf(getc(w2, k), v.z, acc.z);
            acc.w = fmaf(getc(w3, k), v.w, acc.w);
        }
        *(float4*)&out[((size_t)tq * 4 + o) * ED + e4] = silu4(acc);
    }
}

// ---------------------------------------------------------------------------
// Selective scan + gating (R12 layout). One warp = 4 channels; 8 lanes per
// channel, each lane owns an adjacent state pair (LDG.64 B/C). 8-token
// software pipeline with PING-PONG register buffers (unroll-2 chunk loop
// makes the buffer index compile-time — removes the 7 copy-movs per token
// that the shift-style pipeline paid). z half already silu'd (SILUZ).
// ---------------------------------------------------------------------------
__global__ __launch_bounds__(128) void scan_kernel(
    const float* __restrict__ delta,
    const float* __restrict__ xi,
    const float* __restrict__ dbc,
    const float* __restrict__ xz,
    const float* __restrict__ A_log,
    const float* __restrict__ Dp,
    float* __restrict__ y)
{
    const int lane = threadIdx.x & 31;
    const int warp = threadIdx.x >> 5;
    const int ch = lane >> 3;                 // channel within warp
    const int j  = lane & 7;                  // state pair (2j, 2j+1)
    const int c = blockIdx.x * 16 + warp * 4 + ch;
    const int b = c >> 10;
    const int e = c & (ED - 1);

    const float a0 = -__expf(A_log[e * DSTATE + 2 * j]);
    const float a1 = -__expf(A_log[e * DSTATE + 2 * j + 1]);
    const float Dv = Dp[e];

    const float* dptr = delta + (size_t)b * SEQL * ED + e;
    const float* xptr = xi    + (size_t)b * SEQL * ED + e;
    const float* bcp  = dbc   + (size_t)b * SEQL * 64 + DTRANK + 2 * j;
    const float* zptr = xz    + (size_t)b * SEQL * (2 * ED) + ED + e;
    float*       yptr = y     + (size_t)b * SEQL * ED + e;

    constexpr int PF = 8;
    constexpr int NCHUNK = SEQL / PF;
    float cdv[2][PF], cxv[2][PF], czv[2][PF];
    float2 cB[2][PF], cC[2][PF];

    // preload chunk 0 into slot 0
    #pragma unroll
    for (int i = 0; i < PF; i++) {
        cdv[0][i] = __ldg(&dptr[(size_t)i * ED]);
        cxv[0][i] = __ldg(&xptr[(size_t)i * ED]);
        czv[0][i] = __ldg(&zptr[(size_t)i * (2 * ED)]);
        cB[0][i] = __ldg((const float2*)&bcp[i * 64]);
        cC[0][i] = __ldg((const float2*)&bcp[i * 64 + DSTATE]);
    }

    float h0 = 0.f, h1 = 0.f;
    #pragma unroll 2
    for (int cc = 0; cc < NCHUNK; cc++) {
        const int cur = cc & 1, nxt = cur ^ 1;
        const int t0 = cc * PF;
        if (cc + 1 < NCHUNK) {
            #pragma unroll
            for (int i = 0; i < PF; i++) {
                const int t = t0 + PF + i;
                cdv[nxt][i] = __ldg(&dptr[(size_t)t * ED]);
                cxv[nxt][i] = __ldg(&xptr[(size_t)t * ED]);
                czv[nxt][i] = __ldg(&zptr[(size_t)t * (2 * ED)]);
                cB[nxt][i] = __ldg((const float2*)&bcp[t * 64]);
                cC[nxt][i] = __ldg((const float2*)&bcp[t * 64 + DSTATE]);
            }
        }
        #pragma unroll
        for (int i = 0; i < PF; i++) {
            const float dA0 = __expf(cdv[cur][i] * a0);
            const float dA1 = __expf(cdv[cur][i] * a1);
            const float u = cdv[cur][i] * cxv[cur][i];
            h0 = fmaf(dA0, h0, u * cB[cur][i].x);
            h1 = fmaf(dA1, h1, u * cB[cur][i].y);
            float p = fmaf(h1, cC[cur][i].y, h0 * cC[cur][i].x);
            p += __shfl_xor_sync(0xffffffffu, p, 4);
            p += __shfl_xor_sync(0xffffffffu, p, 2);
            p += __shfl_xor_sync(0xffffffffu, p, 1);
            if (j == 0) {
                // czv already = silu(z) (applied in in_proj epilogue)
                yptr[(size_t)(t0 + i) * ED] = (p + Dv * cxv[cur][i]) * czv[cur][i];
            }
        }
    }
}

// ---------------------------------------------------------------------------
// Host launch
// ---------------------------------------------------------------------------
extern "C" void kernel_launch(void* const* d_in, const int* in_sizes, int n_in,
                              void* d_out, int out_size)
{
    const float* x        = (const float*)d_in[0];
    const float* emb_w    = (const float*)d_in[1];
    const float* emb_b    = (const float*)d_in[2];
    const float* in_w     = (const float*)d_in[3];
    const float* conv_w   = (const float*)d_in[4];
    const float* conv_b   = (const float*)d_in[5];
    const float* xp_w     = (const float*)d_in[6];
    const float* dt_w     = (const float*)d_in[7];
    const float* dt_b     = (const float*)d_in[8];
    const float* A_log    = (const float*)d_in[9];
    const float* Dparam   = (const float*)d_in[10];
    const float* out_w    = (const float*)d_in[11];
    const float* norm_w   = (const float*)d_in[12];
    float* h = (float*)d_out;

    float *xz, *xic, *dbc, *dbcp, *delta, *yb;
    cudaGetSymbolAddress((void**)&xz,    g_xz);
    cudaGetSymbolAddress((void**)&xic,   g_xic);
    cudaGetSymbolAddress((void**)&dbc,   g_dbc);
    cudaGetSymbolAddress((void**)&dbcp,  g_dbcp);
    cudaGetSymbolAddress((void**)&delta, g_delta);
    cudaGetSymbolAddress((void**)&yb,    g_y);

    // Embedding: h = x @ emb_w^T + emb_b  (M=4096, N=512, K=64)
    fgemm<128, true, false, false, false, false>
        <<<dim3(DMODEL / 128, NTOK / 128), 256>>>(
        x, 64, emb_w, 64, emb_b, nullptr, h, DMODEL, 64);

    for (int layer = 0; layer < NLAYERS; layer++) {
        const float* l_in_w   = in_w   + (size_t)layer * 2 * ED * DMODEL;
        const float* l_conv_w = conv_w + (size_t)layer * ED * DCONV;
        const float* l_conv_b = conv_b + (size_t)layer * ED;
        const float* l_xp_w   = xp_w   + (size_t)layer * 64 * ED;
        const float* l_dt_w   = dt_w   + (size_t)layer * ED * DTRANK;
        const float* l_dt_b   = dt_b   + (size_t)layer * ED;
        const float* l_A_log  = A_log  + (size_t)layer * ED * DSTATE;
        const float* l_D      = Dparam + (size_t)layer * ED;
        const float* l_out_w  = out_w  + (size_t)layer * DMODEL * ED;
        const float* l_norm_w = norm_w + (size_t)layer * DMODEL;

        // 1+2. xz = rmsnorm(h) @ in_proj^T, norm fused; z half gets silu
        //      in the epilogue (M=4096, N=2048, K=512)
        fgemm<128, false, false, false, true, true, 1, true>
            <<<dim3(2 * ED / 128, NTOK / 128), 256>>>(
            h, DMODEL, l_in_w, DMODEL, nullptr, l_norm_w, xz, 2 * ED, DMODEL);

        // 3. xi = silu(conv(xz[:, :ED]) + cb)
        conv_kernel<<<(NTOK / 4) * (ED / 4) / 256, 256>>>(
            xz, l_conv_w, l_conv_b, xic);

        // 4. dbc = xi @ x_proj^T  (M=4096, N=64, K=1024) — split-K=8
        fgemm<64, false, false, false, false, false, 8>
            <<<dim3(1, NTOK / 128, 8), 256>>>(
            xic, ED, l_xp_w, ED, nullptr, nullptr, dbcp, 64, ED);
        reduce8_kernel<<<(NTOK * 64 / 4) / 256, 256>>>(dbcp, dbc);

        // 5. delta = softplus(dbc[:, :32] @ dt_proj^T + dt_b)  (M=4096, N=1024, K=32)
        fgemm<128, true, false, true, false, false>
            <<<dim3(ED / 128, NTOK / 128), 256>>>(
            dbc, 64, l_dt_w, DTRANK, l_dt_b, nullptr, delta, ED, DTRANK);

        // 6. scan + gating -> y  (z pre-silu'd)
        scan_kernel<<<(BATCH * ED) / 16, 128>>>(delta, xic, dbc, xz,
                                                l_A_log, l_D, yb);

        // 7. h += y @ out_proj^T  (M=4096, N=512, K=1024)
        fgemm<128, false, true, false, false, false>
            <<<dim3(DMODEL / 128, NTOK / 128), 256>>>(
            yb, ED, l_out_w, ED, nullptr, nullptr, h, DMODEL, ED);
    }
}

// round 17
// speedup vs baseline: 1.1493x; 1.1353x over previous
#include <cuda_runtime.h>
#include <math.h>
#include <cstdint>

// Problem constants
#define BATCH 2
#define SEQL 2048
#define NTOK (BATCH * SEQL)          // 4096
#define DMODEL 512
#define ED 1024
#define DSTATE 16
#define DCONV 4
#define DTRANK 32
#define NLAYERS 2
#define NCHAN (BATCH * ED)           // 2048 scan channels
#define CS 512                       // scan chunk size
#define NCH (SEQL / CS)              // 4 chunks

// Scratch buffers (no cudaMalloc allowed)
__device__ float g_xz[NTOK * 2 * ED];
__device__ float g_xic[NTOK * ED];
__device__ float g_dbc[NTOK * 64];
__device__ float g_dbcp[8 * NTOK * 64];   // split-K partials for x_proj
__device__ float g_delta[NTOK * ED];
__device__ float g_y[NTOK * ED];
// chunked-scan intermediates: per (channel, chunk 0..2, state-pair)
__device__ float2 g_scs[NCHAN * 3 * 8];   // local chunk end states
__device__ float2 g_dap[NCHAN * 3 * 8];   // per-chunk prod(dA)
__device__ float2 g_h0b[NCHAN * 3 * 8];   // start states for chunks 1..3

__device__ __forceinline__ float softplus_f(float v) {
    return (v > 20.f) ? v : log1pf(__expf(v));
}
__device__ __forceinline__ float silu_f(float v) {
    return __fdividef(v, 1.f + __expf(-v));
}

// ---------------------------------------------------------------------------
// Packed fp32 helpers (Blackwell f32x2)
// ---------------------------------------------------------------------------
typedef unsigned long long u64t;

__device__ __forceinline__ u64t dup2f(float v) {
    u64t r; unsigned u = __float_as_uint(v);
    asm("mov.b64 %0, {%1, %1};" : "=l"(r) : "r"(u));
    return r;
}
__device__ __forceinline__ void ffma2(u64t& c, u64t a, u64t b) {
    asm("fma.rn.f32x2 %0, %1, %2, %0;" : "+l"(c) : "l"(a), "l"(b));
}
__device__ __forceinline__ float2 unpack2(u64t p) {
    unsigned lo, hi;
    asm("mov.b64 {%0, %1}, %2;" : "=r"(lo), "=r"(hi) : "l"(p));
    return make_float2(__uint_as_float(lo), __uint_as_float(hi));
}

// ---------------------------------------------------------------------------
// fp32 FFMA2 GEMM:  C[M,N] (=, +=) A[M,K] @ W[N,K]^T   (R12 configuration)
// BM=128, BN=TILE_N (128/64), BK=16, 256 threads, smem k-major double buffer,
// two __syncthreads per k-tile. B-fragment columns split into 4-wide groups
// 32 apart (TC=8): conflict-free LDS.128.
// Options: +bias, +softplus, NORMW, ROWSCALE, SPLITK, SILUZ (silu on n0>=ED).
// ---------------------------------------------------------------------------
template <int TILE_N, bool BIAS, bool ACCUM, bool SOFTPLUS, bool NORMW,
          bool ROWSCALE, int SPLITK = 1, bool SILUZ = false>
__global__ __launch_bounds__(256) void fgemm(
    const float* __restrict__ A, int lda,
    const float* __restrict__ W, int ldw,
    const float* __restrict__ bias,
    const float* __restrict__ nw,
    float* __restrict__ C, int ldc, int K)
{
    constexpr int BK = 16, STA = 132, STB = TILE_N + 4;
    constexpr int NBCH = TILE_N / 64;
    constexpr int TC = TILE_N / 16;
    constexpr int NQ = TC / 4;

    __shared__ float sA[2][BK * STA];
    __shared__ float sB[2][BK * STB];
    __shared__ float rbuf[128];

    const int tid = threadIdx.x;
    const int wid = tid >> 5, lane = tid & 31;
    const int ly = lane >> 3, lx = lane & 7;
    const int wy = wid >> 1, wx = wid & 1;
    const int rb = wy * 32 + ly * 8;
    const int cbase = wx * (TILE_N / 2) + lx * 4;
    const int m0 = blockIdx.y * 128;
    const int n0 = blockIdx.x * TILE_N;

    if (SPLITK > 1) {
        const int ks = blockIdx.z * (K / SPLITK);
        A += ks; W += ks;
        C += (size_t)blockIdx.z * gridDim.y * 128 * ldc;
        K = K / SPLITK;
    }

    const int arow = tid >> 2, aq = tid & 3;

    u64t cpk[4][TC] = {};
    float sq0 = 0.f, sq1 = 0.f;
    const int KT = K / BK;

    float4 va0, va1, vb0, vnw;
    float4 vb1 = make_float4(0.f, 0.f, 0.f, 0.f);
    va0 = *(const float4*)&A[(size_t)(m0 + arow) * lda + aq * 4];
    va1 = *(const float4*)&A[(size_t)(m0 + arow + 64) * lda + aq * 4];
    vb0 = *(const float4*)&W[(size_t)(n0 + arow) * ldw + aq * 4];
    if (NBCH == 2) vb1 = *(const float4*)&W[(size_t)(n0 + arow + 64) * ldw + aq * 4];
    if (NORMW) vnw = *(const float4*)&nw[aq * 4];

    for (int kt = 0; kt < KT; kt++) {
        const int buf = kt & 1;
        {
            float* d0 = &sA[buf][(aq * 4) * STA + arow];
            d0[0] = va0.x; d0[STA] = va0.y; d0[2 * STA] = va0.z; d0[3 * STA] = va0.w;
            float* d1 = d0 + 64;
            d1[0] = va1.x; d1[STA] = va1.y; d1[2 * STA] = va1.z; d1[3 * STA] = va1.w;
        }
        if (ROWSCALE) {
            sq0 = fmaf(va0.x, va0.x, fmaf(va0.y, va0.y,
                  fmaf(va0.z, va0.z, fmaf(va0.w, va0.w, sq0))));
            sq1 = fmaf(va1.x, va1.x, fmaf(va1.y, va1.y,
                  fmaf(va1.z, va1.z, fmaf(va1.w, va1.w, sq1))));
        }
        {
            float4 b0 = vb0, b1 = vb1;
            if (NORMW) {
                b0.x *= vnw.x; b0.y *= vnw.y; b0.z *= vnw.z; b0.w *= vnw.w;
                if (NBCH == 2) {
                    b1.x *= vnw.x; b1.y *= vnw.y; b1.z *= vnw.z; b1.w *= vnw.w;
                }
            }
            float* d0 = &sB[buf][(aq * 4) * STB + arow];
            d0[0] = b0.x; d0[STB] = b0.y; d0[2 * STB] = b0.z; d0[3 * STB] = b0.w;
            if (NBCH == 2) {
                float* d1 = d0 + 64;
                d1[0] = b1.x; d1[STB] = b1.y; d1[2 * STB] = b1.z; d1[3 * STB] = b1.w;
            }
        }
        __syncthreads();

        if (kt + 1 < KT) {
            const int k0 = (kt + 1) * BK;
            va0 = *(const float4*)&A[(size_t)(m0 + arow) * lda + k0 + aq * 4];
            va1 = *(const float4*)&A[(size_t)(m0 + arow + 64) * lda + k0 + aq * 4];
            vb0 = *(const float4*)&W[(size_t)(n0 + arow) * ldw + k0 + aq * 4];
            if (NBCH == 2)
                vb1 = *(const float4*)&W[(size_t)(n0 + arow + 64) * ldw + k0 + aq * 4];
            if (NORMW) vnw = *(const float4*)&nw[k0 + aq * 4];
        }

        const float* bufA = sA[buf];
        const float* bufB = sB[buf];
        #pragma unroll
        for (int k = 0; k < BK; k++) {
            const ulonglong2 a0 = *(const ulonglong2*)&bufA[k * STA + rb];
            const ulonglong2 a1 = *(const ulonglong2*)&bufA[k * STA + rb + 4];
            const u64t ap[4] = {a0.x, a0.y, a1.x, a1.y};
            float4 b0 = *(const float4*)&bufB[k * STB + cbase];
            float4 b1;
            if (NQ == 2) b1 = *(const float4*)&bufB[k * STB + cbase + 32];
            u64t bd[TC];
            bd[0] = dup2f(b0.x); bd[1] = dup2f(b0.y);
            bd[2] = dup2f(b0.z); bd[3] = dup2f(b0.w);
            if (NQ == 2) {
                bd[4] = dup2f(b1.x); bd[5] = dup2f(b1.y);
                bd[6] = dup2f(b1.z); bd[7] = dup2f(b1.w);
            }
            #pragma unroll
            for (int ih = 0; ih < 4; ih++)
                #pragma unroll
                for (int j = 0; j < TC; j++)
                    ffma2(cpk[ih][j], ap[ih], bd[j]);
        }
        __syncthreads();
    }

    if (ROWSCALE) {
        float s0 = sq0 + __shfl_xor_sync(0xffffffffu, sq0, 1);
        s0 += __shfl_xor_sync(0xffffffffu, s0, 2);
        float s1 = sq1 + __shfl_xor_sync(0xffffffffu, sq1, 1);
        s1 += __shfl_xor_sync(0xffffffffu, s1, 2);
        if ((lane & 3) == 0) {
            rbuf[arow]      = rsqrtf(s0 / (float)K + 1e-5f);
            rbuf[arow + 64] = rsqrtf(s1 / (float)K + 1e-5f);
        }
        __syncthreads();
    }

    const bool do_silu = SILUZ && (n0 >= ED);

    float bias_r[TC];
    if (BIAS) {
        #pragma unroll
        for (int q = 0; q < NQ; q++) {
            float4 bb = *(const float4*)&bias[n0 + cbase + q * 32];
            bias_r[q * 4 + 0] = bb.x; bias_r[q * 4 + 1] = bb.y;
            bias_r[q * 4 + 2] = bb.z; bias_r[q * 4 + 3] = bb.w;
        }
    }
    #pragma unroll
    for (int ih = 0; ih < 4; ih++) {
        float lo[TC], hi[TC];
        #pragma unroll
        for (int j = 0; j < TC; j++) {
            float2 f = unpack2(cpk[ih][j]);
            lo[j] = f.x; hi[j] = f.y;
        }
        #pragma unroll
        for (int half = 0; half < 2; half++) {
            const float* src = half ? hi : lo;
            const int rt = rb + 2 * ih + half;
            const int row = m0 + rt;
            const float scale = ROWSCALE ? rbuf[rt] : 1.f;
            #pragma unroll
            for (int q = 0; q < NQ; q++) {
                float* cp = &C[(size_t)row * ldc + n0 + cbase + q * 32];
                float4 v = make_float4(src[q * 4 + 0], src[q * 4 + 1],
                                       src[q * 4 + 2], src[q * 4 + 3]);
                if (ROWSCALE) { v.x *= scale; v.y *= scale; v.z *= scale; v.w *= scale; }
                if (BIAS) {
                    v.x += bias_r[q * 4 + 0]; v.y += bias_r[q * 4 + 1];
                    v.z += bias_r[q * 4 + 2]; v.w += bias_r[q * 4 + 3];
                }
                if (SOFTPLUS) {
                    v.x = softplus_f(v.x); v.y = softplus_f(v.y);
                    v.z = softplus_f(v.z); v.w = softplus_f(v.w);
                }
                if (SILUZ) {
                    if (do_silu) {
                        v.x = silu_f(v.x); v.y = silu_f(v.y);
                        v.z = silu_f(v.z); v.w = silu_f(v.w);
                    }
                }
                if (ACCUM) {
                    float4 o = *(const float4*)cp;
                    v.x += o.x; v.y += o.y; v.z += o.z; v.w += o.w;
                }
                *(float4*)cp = v;
            }
        }
    }
}

// ---------------------------------------------------------------------------
// Reduce 8 split-K partials: out[i] = sum_s part[s][i]  (float4-wide)
// ---------------------------------------------------------------------------
__global__ void reduce8_kernel(const float* __restrict__ part,
                               float* __restrict__ out)
{
    const int i = (blockIdx.x * 256 + threadIdx.x) * 4;
    const int n = NTOK * 64;
    float4 s = *(const float4*)&part[i];
    #pragma unroll
    for (int k = 1; k < 8; k++) {
        float4 v = *(const float4*)&part[i + k * n];
        s.x += v.x; s.y += v.y; s.z += v.z; s.w += v.w;
    }
    *(float4*)&out[i] = s;
}

// ---------------------------------------------------------------------------
// Depthwise causal conv (k=4) + bias + silu (fast-div).
// Each thread: 4 consecutive tokens x 4 channels (7 float4 loads, 16 outputs).
// ---------------------------------------------------------------------------
__device__ __forceinline__ float getc(float4 v, int k) {
    return k == 0 ? v.x : k == 1 ? v.y : k == 2 ? v.z : v.w;
}
__device__ __forceinline__ float4 silu4(float4 a) {
    a.x = silu_f(a.x); a.y = silu_f(a.y);
    a.z = silu_f(a.z); a.w = silu_f(a.w);
    return a;
}

__global__ void conv_kernel(const float* __restrict__ xz,
                            const float* __restrict__ cw,
                            const float* __restrict__ cb,
                            float* __restrict__ out)
{
    const int idx = blockIdx.x * blockDim.x + threadIdx.x;   // NTOK/4 * ED/4
    const int e4 = (idx & 255) << 2;
    const int tq = idx >> 8;                 // token quad
    const int tloc = (tq * 4) & (SEQL - 1);  // local pos of first token

    const float4 bias = *(const float4*)&cb[e4];
    const float4 w0 = *(const float4*)&cw[(e4 + 0) * DCONV];
    const float4 w1 = *(const float4*)&cw[(e4 + 1) * DCONV];
    const float4 w2 = *(const float4*)&cw[(e4 + 2) * DCONV];
    const float4 w3 = *(const float4*)&cw[(e4 + 3) * DCONV];

    float4 xv[7];
    #pragma unroll
    for (int s = 0; s < 7; s++) {
        const int tl = tloc - 3 + s;
        xv[s] = (tl >= 0)
            ? *(const float4*)&xz[((size_t)tq * 4 + (s - 3)) * (2 * ED) + e4]
            : make_float4(0.f, 0.f, 0.f, 0.f);
    }

    #pragma unroll
    for (int o = 0; o < 4; o++) {
        float4 acc = bias;
        #pragma unroll
        for (int k = 0; k < DCONV; k++) {
            const float4 v = xv[o + k];
            acc.x = fmaf(getc(w0, k), v.x, acc.x);
            acc.y = fmaf(getc(w1, k), v.y, acc.y);
            acc.z = fmaf(getc(w2, k), v.z, acc.z);
            acc.w = fmaf(getc(w3, k), v.w, acc.w);
        }
        *(float4*)&out[((size_t)tq * 4 + o) * ED + e4] = silu4(acc);
    }
}

// ---------------------------------------------------------------------------
// Chunked scan pass 1: local states. For chunks 0..2, compute the chunk-local
// end state (h starting from 0) and prod(dA) per (channel, state pair).
// Warp layout identical to R12 scan: 4 channels x (8 lanes x 2 states).
// ---------------------------------------------------------------------------
__global__ __launch_bounds__(128) void scan_state_kernel(
    const float* __restrict__ delta,
    const float* __restrict__ xi,
    const float* __restrict__ dbc,
    const float* __restrict__ A_log,
    float2* __restrict__ scs,
    float2* __restrict__ dap)
{
    const int lane = threadIdx.x & 31;
    const int warp = threadIdx.x >> 5;
    const int ch = lane >> 3;
    const int j  = lane & 7;
    const int chunk = blockIdx.x >> 7;        // 0..2
    const int cblk = blockIdx.x & 127;
    const int c = cblk * 16 + warp * 4 + ch;
    const int b = c >> 10;
    const int e = c & (ED - 1);

    const float a0 = -__expf(A_log[e * DSTATE + 2 * j]);
    const float a1 = -__expf(A_log[e * DSTATE + 2 * j + 1]);

    const size_t tb = (size_t)b * SEQL + chunk * CS;
    const float* dptr = delta + tb * ED + e;
    const float* xptr = xi    + tb * ED + e;
    const float* bcp  = dbc   + tb * 64 + DTRANK + 2 * j;

    constexpr int PF = 8;
    float cdv[PF], cxv[PF];
    float2 cB[PF];
    #pragma unroll
    for (int i = 0; i < PF; i++) {
        cdv[i] = __ldg(&dptr[(size_t)i * ED]);
        cxv[i] = __ldg(&xptr[(size_t)i * ED]);
        cB[i] = __ldg((const float2*)&bcp[i * 64]);
    }

    float h0 = 0.f, h1 = 0.f, p0 = 1.f, p1 = 1.f;
    for (int t0 = 0; t0 < CS; t0 += PF) {
        float ndv[PF], nxv[PF];
        float2 nB[PF];
        if (t0 + PF < CS) {
            #pragma unroll
            for (int i = 0; i < PF; i++) {
                const int t = t0 + PF + i;
                ndv[i] = __ldg(&dptr[(size_t)t * ED]);
                nxv[i] = __ldg(&xptr[(size_t)t * ED]);
                nB[i] = __ldg((const float2*)&bcp[t * 64]);
            }
        }
        #pragma unroll
        for (int i = 0; i < PF; i++) {
            const float dA0 = __expf(cdv[i] * a0);
            const float dA1 = __expf(cdv[i] * a1);
            const float u = cdv[i] * cxv[i];
            h0 = fmaf(dA0, h0, u * cB[i].x);
            h1 = fmaf(dA1, h1, u * cB[i].y);
            p0 *= dA0; p1 *= dA1;
        }
        #pragma unroll
        for (int i = 0; i < PF; i++) {
            cdv[i] = ndv[i]; cxv[i] = nxv[i]; cB[i] = nB[i];
        }
    }

    const int idx = (c * 3 + chunk) * 8 + j;
    scs[idx] = make_float2(h0, h1);
    dap[idx] = make_float2(p0, p1);
}

// ---------------------------------------------------------------------------
// Chunked scan pass 2: sequential combine over the 3 chunk boundaries.
// h_start(k+1) = dap(k) * h_start(k) + scs(k). One thread per (channel, pair).
// ---------------------------------------------------------------------------
__global__ void scan_combine_kernel(const float2* __restrict__ scs,
                                    const float2* __restrict__ dap,
                                    float2* __restrict__ h0b)
{
    const int idx = blockIdx.x * 256 + threadIdx.x;   // over NCHAN*8
    const int c = idx >> 3, j = idx & 7;
    float hx = 0.f, hy = 0.f;
    #pragma unroll
    for (int k = 0; k < 3; k++) {
        const int q = (c * 3 + k) * 8 + j;
        const float2 s = scs[q];
        const float2 p = dap[q];
        hx = fmaf(p.x, hx, s.x);
        hy = fmaf(p.y, hy, s.y);
        h0b[q] = make_float2(hx, hy);
    }
}

// ---------------------------------------------------------------------------
// Chunked scan pass 3: full scan within each chunk from its true start state,
// writing gated y. 4 chunks in parallel -> 4x the warps of the monolithic
// scan. Body identical to the R12 scan. z half already silu'd (SILUZ).
// ---------------------------------------------------------------------------
__global__ __launch_bounds__(128) void scan_y_kernel(
    const float* __restrict__ delta,
    const float* __restrict__ xi,
    const float* __restrict__ dbc,
    const float* __restrict__ xz,
    const float* __restrict__ A_log,
    const float* __restrict__ Dp,
    const float2* __restrict__ h0b,
    float* __restrict__ y)
{
    const int lane = threadIdx.x & 31;
    const int warp = threadIdx.x >> 5;
    const int ch = lane >> 3;
    const int j  = lane & 7;
    const int chunk = blockIdx.x >> 7;        // 0..3
    const int cblk = blockIdx.x & 127;
    const int c = cblk * 16 + warp * 4 + ch;
    const int b = c >> 10;
    const int e = c & (ED - 1);

    const float a0 = -__expf(A_log[e * DSTATE + 2 * j]);
    const float a1 = -__expf(A_log[e * DSTATE + 2 * j + 1]);
    const float Dv = Dp[e];

    const size_t tb = (size_t)b * SEQL + chunk * CS;
    const float* dptr = delta + tb * ED + e;
    const float* xptr = xi    + tb * ED + e;
    const float* bcp  = dbc   + tb * 64 + DTRANK + 2 * j;
    const float* zptr = xz    + tb * (2 * ED) + ED + e;
    float*       yptr = y     + tb * ED + e;

    float h0 = 0.f, h1 = 0.f;
    if (chunk > 0) {
        const float2 hh = h0b[(c * 3 + chunk - 1) * 8 + j];
        h0 = hh.x; h1 = hh.y;
    }

    constexpr int PF = 8;
    float cdv[PF], cxv[PF], czv[PF];
    float2 cB[PF], cC[PF];
    #pragma unroll
    for (int i = 0; i < PF; i++) {
        cdv[i] = __ldg(&dptr[(size_t)i * ED]);
        cxv[i] = __ldg(&xptr[(size_t)i * ED]);
        czv[i] = __ldg(&zptr[(size_t)i * (2 * ED)]);
        cB[i] = __ldg((const float2*)&bcp[i * 64]);
        cC[i] = __ldg((const float2*)&bcp[i * 64 + DSTATE]);
    }

    for (int t0 = 0; t0 < CS; t0 += PF) {
        float ndv[PF], nxv[PF], nzv[PF];
        float2 nB[PF], nC[PF];
        if (t0 + PF < CS) {
            #pragma unroll
            for (int i = 0; i < PF; i++) {
                const int t = t0 + PF + i;
                ndv[i] = __ldg(&dptr[(size_t)t * ED]);
                nxv[i] = __ldg(&xptr[(size_t)t * ED]);
                nzv[i] = __ldg(&zptr[(size_t)t * (2 * ED)]);
                nB[i] = __ldg((const float2*)&bcp[t * 64]);
                nC[i] = __ldg((const float2*)&bcp[t * 64 + DSTATE]);
            }
        }
        #pragma unroll
        for (int i = 0; i < PF; i++) {
            const float dA0 = __expf(cdv[i] * a0);
            const float dA1 = __expf(cdv[i] * a1);
            const float u = cdv[i] * cxv[i];
            h0 = fmaf(dA0, h0, u * cB[i].x);
            h1 = fmaf(dA1, h1, u * cB[i].y);
            float p = fmaf(h1, cC[i].y, h0 * cC[i].x);
            p += __shfl_xor_sync(0xffffffffu, p, 4);
            p += __shfl_xor_sync(0xffffffffu, p, 2);
            p += __shfl_xor_sync(0xffffffffu, p, 1);
            if (j == 0) {
                yptr[(size_t)(t0 + i) * ED] = (p + Dv * cxv[i]) * czv[i];
            }
        }
        #pragma unroll
        for (int i = 0; i < PF; i++) {
            cdv[i] = ndv[i]; cxv[i] = nxv[i]; czv[i] = nzv[i];
            cB[i] = nB[i]; cC[i] = nC[i];
        }
    }
}

// ---------------------------------------------------------------------------
// Host launch
// ---------------------------------------------------------------------------
extern "C" void kernel_launch(void* const* d_in, const int* in_sizes, int n_in,
                              void* d_out, int out_size)
{
    const float* x        = (const float*)d_in[0];
    const float* emb_w    = (const float*)d_in[1];
    const float* emb_b    = (const float*)d_in[2];
    const float* in_w     = (const float*)d_in[3];
    const float* conv_w   = (const float*)d_in[4];
    const float* conv_b   = (const float*)d_in[5];
    const float* xp_w     = (const float*)d_in[6];
    const float* dt_w     = (const float*)d_in[7];
    const float* dt_b     = (const float*)d_in[8];
    const float* A_log    = (const float*)d_in[9];
    const float* Dparam   = (const float*)d_in[10];
    const float* out_w    = (const float*)d_in[11];
    const float* norm_w   = (const float*)d_in[12];
    float* h = (float*)d_out;

    float *xz, *xic, *dbc, *dbcp, *delta, *yb;
    float2 *scs, *dap, *h0b;
    cudaGetSymbolAddress((void**)&xz,    g_xz);
    cudaGetSymbolAddress((void**)&xic,   g_xic);
    cudaGetSymbolAddress((void**)&dbc,   g_dbc);
    cudaGetSymbolAddress((void**)&dbcp,  g_dbcp);
    cudaGetSymbolAddress((void**)&delta, g_delta);
    cudaGetSymbolAddress((void**)&yb,    g_y);
    cudaGetSymbolAddress((void**)&scs,   g_scs);
    cudaGetSymbolAddress((void**)&dap,   g_dap);
    cudaGetSymbolAddress((void**)&h0b,   g_h0b);

    // Embedding: h = x @ emb_w^T + emb_b  (M=4096, N=512, K=64)
    fgemm<128, true, false, false, false, false>
        <<<dim3(DMODEL / 128, NTOK / 128), 256>>>(
        x, 64, emb_w, 64, emb_b, nullptr, h, DMODEL, 64);

    for (int layer = 0; layer < NLAYERS; layer++) {
        const float* l_in_w   = in_w   + (size_t)layer * 2 * ED * DMODEL;
        const float* l_conv_w = conv_w + (size_t)layer * ED * DCONV;
        const float* l_conv_b = conv_b + (size_t)layer * ED;
        const float* l_xp_w   = xp_w   + (size_t)layer * 64 * ED;
        const float* l_dt_w   = dt_w   + (size_t)layer * ED * DTRANK;
        const float* l_dt_b   = dt_b   + (size_t)layer * ED;
        const float* l_A_log  = A_log  + (size_t)layer * ED * DSTATE;
        const float* l_D      = Dparam + (size_t)layer * ED;
        const float* l_out_w  = out_w  + (size_t)layer * DMODEL * ED;
        const float* l_norm_w = norm_w + (size_t)layer * DMODEL;

        // 1+2. xz = rmsnorm(h) @ in_proj^T, norm fused; z half gets silu
        //      in the epilogue (M=4096, N=2048, K=512)
        fgemm<128, false, false, false, true, true, 1, true>
            <<<dim3(2 * ED / 128, NTOK / 128), 256>>>(
            h, DMODEL, l_in_w, DMODEL, nullptr, l_norm_w, xz, 2 * ED, DMODEL);

        // 3. xi = silu(conv(xz[:, :ED]) + cb)
        conv_kernel<<<(NTOK / 4) * (ED / 4) / 256, 256>>>(
            xz, l_conv_w, l_conv_b, xic);

        // 4. dbc = xi @ x_proj^T  (M=4096, N=64, K=1024) — split-K=8
        fgemm<64, false, false, false, false, false, 8>
            <<<dim3(1, NTOK / 128, 8), 256>>>(
            xic, ED, l_xp_w, ED, nullptr, nullptr, dbcp, 64, ED);
        reduce8_kernel<<<(NTOK * 64 / 4) / 256, 256>>>(dbcp, dbc);

        // 5. delta = softplus(dbc[:, :32] @ dt_proj^T + dt_b)  (M=4096, N=1024, K=32)
        fgemm<128, true, false, true, false, false>
            <<<dim3(ED / 128, NTOK / 128), 256>>>(
            dbc, 64, l_dt_w, DTRANK, l_dt_b, nullptr, delta, ED, DTRANK);

        // 6. chunked scan: local states -> combine -> per-chunk scan + gating
        scan_state_kernel<<<3 * (NCHAN / 16), 128>>>(
            delta, xic, dbc, l_A_log, scs, dap);
        scan_combine_kernel<<<(NCHAN * 8) / 256, 256>>>(scs, dap, h0b);
        scan_y_kernel<<<NCH * (NCHAN / 16), 128>>>(
            delta, xic, dbc, xz, l_A_log, l_D, h0b, yb);

        // 7. h += y @ out_proj^T  (M=4096, N=512, K=1024)
        fgemm<128, false, true, false, false, false>
            <<<dim3(DMODEL / 128, NTOK / 128), 256>>>(
            yb, ED, l_out_w, ED, nullptr, nullptr, h, DMODEL, ED);
    }
}